// round 1
// baseline (speedup 1.0000x reference)
#include <cuda_runtime.h>
#include <math.h>

#define INFV 1e10f
#define NB    8
#define NSEQ  1024
#define NDIM  64
#define NPAIR 5
#define NPB   40               // pair*8 + batch
#define NDIAG 2047

// tensor order matches d_in: 0=TGT, 1=OTH, 2=X
__constant__ int c_pa[NPAIR] = {2, 0, 0, 1, 1};  // first arg (rows i)
__constant__ int c_pb[NPAIR] = {2, 2, 0, 2, 1};  // second arg (rows j)

// scratch (static device allocations are allowed)
__device__ float g_norm[3 * NB * NSEQ * NDIM];                 // ~6 MB
__device__ float g_diag[(size_t)NPB * NDIAG * NSEQ];           // ~335 MB, diag-major cost
__device__ float g_sdtw[NPB];

// ---------------------------------------------------------------------------
// Kernel 1: row-normalize all three tensors. One warp per row (D=64 -> float2/lane)
// ---------------------------------------------------------------------------
__global__ void norm_kernel(const float* __restrict__ TGT,
                            const float* __restrict__ OTH,
                            const float* __restrict__ X) {
    int row  = blockIdx.x * 8 + (threadIdx.x >> 5);   // 0 .. 24575
    int lane = threadIdx.x & 31;
    const float* src = (row < 8192) ? TGT : (row < 16384 ? OTH : X);
    int lrow = row & 8191;
    float2 v = reinterpret_cast<const float2*>(src + (size_t)lrow * NDIM)[lane];
    float s = v.x * v.x + v.y * v.y;
    #pragma unroll
    for (int o = 16; o; o >>= 1) s += __shfl_xor_sync(0xffffffffu, s, o);
    float scale = (s > 1e-16f) ? rsqrtf(s) : 1e8f;
    float2 out = make_float2(v.x * scale, v.y * scale);
    reinterpret_cast<float2*>(g_norm + (size_t)row * NDIM)[lane] = out;
}

// ---------------------------------------------------------------------------
// Kernel 2: cost = 1 - A_n . B_n^T per (pair,batch), written DIAGONAL-MAJOR.
// 128x128 output tile per CTA, K=64 in chunks of 16, 256 threads, 8x8 micro.
// Epilogue stages 32-row chunks in SMEM and emits contiguous diagonal runs.
// ---------------------------------------------------------------------------
__global__ void __launch_bounds__(256) cost_kernel() {
    const int pb    = blockIdx.y;           // 0..39
    const int pair  = pb >> 3;
    const int batch = pb & 7;
    const int ti    = blockIdx.x >> 3;
    const int tj    = blockIdx.x & 7;
    const int i0 = ti * 128, j0 = tj * 128;

    const float* Ap = g_norm + ((size_t)(c_pa[pair] * NB + batch)) * NSEQ * NDIM + (size_t)i0 * NDIM;
    const float* Bp = g_norm + ((size_t)(c_pb[pair] * NB + batch)) * NSEQ * NDIM + (size_t)j0 * NDIM;

    __shared__ float sbuf[4608];            // As[16][128] | Bs[16][128] ; reused as Cs[32][136]
    float* As = sbuf;
    float* Bs = sbuf + 2048;

    const int t  = threadIdx.x;
    const int tx = t & 15, ty = t >> 4;

    float acc[8][8];
    #pragma unroll
    for (int u = 0; u < 8; u++)
        #pragma unroll
        for (int v = 0; v < 8; v++) acc[u][v] = 0.f;

    for (int kc = 0; kc < NDIM; kc += 16) {
        __syncthreads();
        #pragma unroll
        for (int q = 0; q < 2; q++) {
            int id = t * 2 + q;             // 0..511
            int r  = id >> 2;               // row within tile
            int kq = id & 3;                // which float4 of the 16-wide K chunk
            float4 va = reinterpret_cast<const float4*>(Ap + r * NDIM + kc)[kq];
            As[(kq * 4 + 0) * 128 + r] = va.x;
            As[(kq * 4 + 1) * 128 + r] = va.y;
            As[(kq * 4 + 2) * 128 + r] = va.z;
            As[(kq * 4 + 3) * 128 + r] = va.w;
            float4 vb = reinterpret_cast<const float4*>(Bp + r * NDIM + kc)[kq];
            Bs[(kq * 4 + 0) * 128 + r] = vb.x;
            Bs[(kq * 4 + 1) * 128 + r] = vb.y;
            Bs[(kq * 4 + 2) * 128 + r] = vb.z;
            Bs[(kq * 4 + 3) * 128 + r] = vb.w;
        }
        __syncthreads();
        #pragma unroll
        for (int kk = 0; kk < 16; kk++) {
            float a[8], b[8];
            *(float4*)(a)     = *(float4*)&As[kk * 128 + ty * 8];
            *(float4*)(a + 4) = *(float4*)&As[kk * 128 + ty * 8 + 4];
            *(float4*)(b)     = *(float4*)&Bs[kk * 128 + tx * 8];
            *(float4*)(b + 4) = *(float4*)&Bs[kk * 128 + tx * 8 + 4];
            #pragma unroll
            for (int u = 0; u < 8; u++)
                #pragma unroll
                for (int v = 0; v < 8; v++) acc[u][v] += a[u] * b[v];
        }
    }

    // epilogue: 4 chunks of 32 rows, diag-major coalesced writes
    float* Cs = sbuf;                       // 32 x 136
    const size_t dbase = (size_t)pb * ((size_t)NDIAG * NSEQ);
    const int wid = t >> 5, lane = t & 31;
    for (int c = 0; c < 4; c++) {
        __syncthreads();
        if ((ty >> 2) == c) {
            int ri = (ty & 3) * 8;
            #pragma unroll
            for (int u = 0; u < 8; u++) {
                *(float4*)&Cs[(ri + u) * 136 + tx * 8]     = *(float4*)&acc[u][0];
                *(float4*)&Cs[(ri + u) * 136 + tx * 8 + 4] = *(float4*)&acc[u][4];
            }
        }
        __syncthreads();
        int kb  = i0 + j0 + c * 32;         // global k of local diag 0
        int gi0 = i0 + c * 32;
        for (int kl = wid; kl < 159; kl += 8) {
            int ri = lane;
            int jl = kl - ri;
            if (jl >= 0 && jl < 128 && ri < 32) {
                g_diag[dbase + (size_t)(kb + kl) * NSEQ + (gi0 + ri)] =
                    1.0f - Cs[ri * 136 + jl];
            }
        }
    }
}

// ---------------------------------------------------------------------------
// Kernel 3: soft-DTW DP over anti-diagonals. One CTA per (pair,batch),
// 1024 threads, thread i = row i. Double-buffered warp-boundary exchange,
// one __syncthreads per step, cost prefetched 2 diagonals ahead.
// ---------------------------------------------------------------------------
__global__ void __launch_bounds__(1024, 1) dp_kernel() {
    const int pb = blockIdx.x;
    const float* __restrict__ diag = g_diag + (size_t)pb * ((size_t)NDIAG * NSEQ);
    const int i    = threadIdx.x;
    const int w    = i >> 5;
    const int lane = i & 31;

    __shared__ float bd1[2][32];
    __shared__ float bd2[2][32];
    if (i < 32) { bd1[0][i] = bd1[1][i] = bd2[0][i] = bd2[1][i] = INFV; }
    __syncthreads();

    float d2 = INFV;   // R on diag k-2, row i
    float d1 = INFV;   // R on diag k-1, row i

    float c0 = diag[i];                 // cost on diag 0 (zeros where invalid; masked)
    float c1 = diag[NSEQ + i];          // cost on diag 1

    for (int k = 0; k < NDIAG; k++) {
        float cnext = (k + 2 < NDIAG) ? diag[(size_t)(k + 2) * NSEQ + i] : 0.f;

        float up = __shfl_up_sync(0xffffffffu, d1, 1);   // R[k-1], row i-1
        float ul = __shfl_up_sync(0xffffffffu, d2, 1);   // R[k-2], row i-1
        const int rb = (k & 1) ^ 1;
        if (lane == 0) {
            up = (w == 0) ? INFV : bd1[rb][w - 1];
            ul = (w == 0) ? ((k == 0) ? 0.f : INFV) : bd2[rb][w - 1];
        }

        float m   = fminf(ul, fminf(up, d1));
        float smn = m - __logf(__expf(m - ul) + __expf(m - up) + __expf(m - d1));
        int   j   = k - i;
        float cur = (j >= 0 && j < NSEQ) ? (c0 + smn) : INFV;

        d2 = d1;
        d1 = cur;
        if (lane == 31) {
            const int wb = k & 1;
            bd1[wb][w] = d1;
            bd2[wb][w] = d2;
        }
        c0 = c1;
        c1 = cnext;
        __syncthreads();
    }

    if (i == NSEQ - 1) g_sdtw[pb] = d1;
}

// ---------------------------------------------------------------------------
// Kernel 4: final MSE reduction
// ---------------------------------------------------------------------------
__global__ void final_kernel(const float* __restrict__ labels, float* __restrict__ out) {
    int b = threadIdx.x;
    float v = 0.f;
    if (b < NB) {
        float sXX = g_sdtw[0 * NB + b];
        float sTX = g_sdtw[1 * NB + b];
        float sTT = g_sdtw[2 * NB + b];
        float sOX = g_sdtw[3 * NB + b];
        float sOO = g_sdtw[4 * NB + b];
        float dt = sTX - 0.5f * (sTT + sXX);
        float dq = sOX - 0.5f * (sOO + sXX);
        float e  = dt - dq - labels[0];
        v = e * e;
    }
    #pragma unroll
    for (int o = 16; o; o >>= 1) v += __shfl_xor_sync(0xffffffffu, v, o);
    if (b == 0) out[0] = v * (1.0f / NB);
}

// ---------------------------------------------------------------------------
extern "C" void kernel_launch(void* const* d_in, const int* in_sizes, int n_in,
                              void* d_out, int out_size) {
    const float* TGT    = (const float*)d_in[0];
    const float* OTH    = (const float*)d_in[1];
    const float* X      = (const float*)d_in[2];
    const float* labels = (const float*)d_in[3];
    float* out = (float*)d_out;

    norm_kernel<<<3072, 256>>>(TGT, OTH, X);
    cost_kernel<<<dim3(64, NPB), 256>>>();
    dp_kernel<<<NPB, 1024>>>();
    final_kernel<<<1, 32>>>(labels, out);
}